// round 2
// baseline (speedup 1.0000x reference)
#include <cuda_runtime.h>
#include <cuda_bf16.h>
#include <cstdint>

// Problem dims
#define Tn   4096
#define INn  32
#define Hn   512
#define OUTn 32

// Launch config
#define G    128      // CTAs (<= 148 SMs, all co-resident)
#define TPB  512      // threads per CTA (16 warps)
#define ROWS 16       // gate rows per CTA = 4 hidden units x 4 gates

// -------- persistent device scratch (no allocations allowed) --------
__device__ float g_X1[(size_t)Tn * 4 * Hn];      // 32 MB: precomputed x-part of layer 1 (incl. bias)
__device__ float g_hseq[3][(size_t)Tn * Hn];     // 24 MB: per-layer hidden sequences

// grid barrier state (self-resetting counters; gen is monotonic across replays)
__device__ __align__(128) unsigned g_cnt2[64];   // [0],[32] used (separate 128B lines)
__device__ __align__(128) unsigned g_genw[32];   // [0] used

__device__ __forceinline__ void grid_barrier(unsigned idx) {
    __syncthreads();
    if (threadIdx.x == 0) {
        volatile unsigned* genp = &g_genw[0];
        unsigned* cntp = &g_cnt2[(idx & 1) * 32];
        unsigned g = *genp;
        unsigned old = atomicAdd(cntp, 1u);
        if (old == G - 1) {
            // last arriver: reset counter for barrier idx+2, then release
            atomicExch(cntp, 0u);
            __threadfence();
            *genp = g + 1;
        } else {
            int it = 0;
            while (*genp == g) {
                if (++it > 32) __nanosleep(64);
            }
        }
        __threadfence();   // acquire for data written before other CTAs' arrivals
    }
    __syncthreads();
}

__device__ __forceinline__ float warp_reduce(float v) {
    v += __shfl_xor_sync(0xffffffffu, v, 16);
    v += __shfl_xor_sync(0xffffffffu, v, 8);
    v += __shfl_xor_sync(0xffffffffu, v, 4);
    v += __shfl_xor_sync(0xffffffffu, v, 2);
    v += __shfl_xor_sync(0xffffffffu, v, 1);
    return v;
}

__device__ __forceinline__ float sigmoidf_(float x) {
    return 1.0f / (1.0f + __expf(-x));
}

__global__ void __launch_bounds__(TPB, 1) lstm_persistent_kernel(
    const float* __restrict__ seq,
    const float* __restrict__ Wih1, const float* __restrict__ Whh1,
    const float* __restrict__ bih1, const float* __restrict__ bhh1,
    const float* __restrict__ Wih2, const float* __restrict__ Whh2,
    const float* __restrict__ bih2, const float* __restrict__ bhh2,
    const float* __restrict__ Wih3, const float* __restrict__ Whh3,
    const float* __restrict__ bih3, const float* __restrict__ bhh3,
    const float* __restrict__ Wout, const float* __restrict__ bout,
    float* __restrict__ out)
{
    __shared__ float smem_h[Hn];         // h(t-1), full 512
    __shared__ float smem_x[Hn];         // prev-layer h(t) for layers 2/3
    __shared__ float smem_g[ROWS];       // activated gates for this CTA's 4 units
    __shared__ float smem_c[4];          // cell state for this CTA's 4 units
    __shared__ float smem_seq[32 * 33];  // padded seq tile for X1 phase

    const int tid  = threadIdx.x;
    const int w    = tid >> 5;
    const int lane = tid & 31;
    const int cta  = blockIdx.x;
    const int hbase = cta * 4;           // 4 hidden units per CTA
    const int ju   = w >> 2;             // 0..3  (hidden unit within CTA)
    const int gate = w & 3;              // 0..3  (i, f, g, o)
    const int row  = gate * Hn + hbase + ju;   // global gate row 0..2047
    unsigned baridx = 0;

    // ================= Phase 0: X1[t][row] = seq[t] . Wih1[row] + (b_ih1+b_hh1)[row] ==========
    // Each CTA computes only its own 16 rows -> no grid barrier needed afterward.
    {
        float wx = Wih1[row * INn + lane];                 // lane l holds Wih1[row][l]
        float b1 = bih1[row] + bhh1[row];
        for (int t0 = 0; t0 < Tn; t0 += 32) {
            __syncthreads();
            if (tid < 256) {
                const float4 v = *(const float4*)(seq + (size_t)t0 * INn + tid * 4);
                int tl = (tid * 4) >> 5, k = (tid * 4) & 31;
                float* p = &smem_seq[tl * 33 + k];
                p[0] = v.x; p[1] = v.y; p[2] = v.z; p[3] = v.w;
            }
            __syncthreads();
            float acc = 0.0f;
            #pragma unroll
            for (int k = 0; k < INn; k++)
                acc = fmaf(__shfl_sync(0xffffffffu, wx, k), smem_seq[lane * 33 + k], acc);
            g_X1[(size_t)(t0 + lane) * (4 * Hn) + row] = acc + b1;
        }
    }

    // ================= Phases 1..3: the three LSTM layers =================
    const float* WihL[3] = {Wih1, Wih2, Wih3};   // [0] unused in recurrence
    const float* WhhL[3] = {Whh1, Whh2, Whh3};
    const float* bihL[3] = {bih1, bih2, bih3};
    const float* bhhL[3] = {bhh1, bhh2, bhh3};

    for (int layer = 0; layer < 3; layer++) {
        // --- load this warp's weight row into registers (lane-strided: conflict-free LDS later)
        float whh[16];
        float wih[16];
        {
            const float* Whh = WhhL[layer];
            #pragma unroll
            for (int i = 0; i < 16; i++) whh[i] = Whh[(size_t)row * Hn + i * 32 + lane];
        }
        if (layer > 0) {
            const float* Wih = WihL[layer];
            #pragma unroll
            for (int i = 0; i < 16; i++) wih[i] = Wih[(size_t)row * Hn + i * 32 + lane];
        } else {
            #pragma unroll
            for (int i = 0; i < 16; i++) wih[i] = 0.0f;
        }
        float bias = (layer > 0) ? (bihL[layer][row] + bhhL[layer][row]) : 0.0f;

        __syncthreads();
        if (tid < 4) smem_c[tid] = 0.0f;
        for (int i = tid; i < Hn; i += TPB) smem_h[i] = 0.0f;   // h(-1) = 0
        __syncthreads();

        float*       hcur  = &g_hseq[layer][0];
        const float* hprev = (layer > 0) ? &g_hseq[layer - 1][0] : nullptr;

        for (int t = 0; t < Tn; t++) {
            if (t > 0) {
                grid_barrier(baridx++);          // all CTAs' h(t-1) chunks are globally visible
                if (tid < 128) {
                    float4 v = *(const float4*)(hcur + (size_t)(t - 1) * Hn + tid * 4);
                    *(float4*)(&smem_h[tid * 4]) = v;
                }
            }
            float xval = 0.0f;
            if (layer == 0) {
                xval = g_X1[(size_t)t * (4 * Hn) + row];   // broadcast LDG (includes bias)
            } else {
                if (tid >= 128 && tid < 256) {
                    int q = tid - 128;
                    float4 v = *(const float4*)(hprev + (size_t)t * Hn + q * 4);
                    *(float4*)(&smem_x[q * 4]) = v;
                }
            }
            __syncthreads();

            // gate row dot product: 512 (Whh) [+ 512 (Wih) for layers 2/3]
            float acc = 0.0f;
            #pragma unroll
            for (int i = 0; i < 16; i++)
                acc = fmaf(whh[i], smem_h[i * 32 + lane], acc);
            if (layer > 0) {
                #pragma unroll
                for (int i = 0; i < 16; i++)
                    acc = fmaf(wih[i], smem_x[i * 32 + lane], acc);
            }
            acc = warp_reduce(acc);

            if (lane == 0) {
                float gv = acc + ((layer == 0) ? xval : bias);
                gv = (gate == 2) ? tanhf(gv) : sigmoidf_(gv);
                smem_g[ju * 4 + gate] = gv;
            }
            __syncthreads();

            if (tid == 0) {
                #pragma unroll
                for (int jj = 0; jj < 4; jj++) {
                    float iv = smem_g[jj * 4 + 0];
                    float fv = smem_g[jj * 4 + 1];
                    float gg = smem_g[jj * 4 + 2];
                    float ov = smem_g[jj * 4 + 3];
                    float c  = fmaf(fv, smem_c[jj], iv * gg);
                    smem_c[jj] = c;
                    hcur[(size_t)t * Hn + hbase + jj] = ov * tanhf(c);
                }
                __threadfence();   // release before barrier arrive (next iteration / layer end)
            }
        }
        grid_barrier(baridx++);    // layer complete: full h sequence visible to next layer
    }

    // ================= Final projection: out[t] = h3[t] . Wout^T + bout =================
    {
        const float* h3 = &g_hseq[2][0];
        for (int t = cta; t < Tn; t += G) {
            #pragma unroll
            for (int oi = 0; oi < 2; oi++) {
                int o = w * 2 + oi;            // 16 warps x 2 = 32 outputs
                float a = 0.0f;
                #pragma unroll
                for (int i = 0; i < 16; i++) {
                    int k = i * 32 + lane;
                    a = fmaf(h3[(size_t)t * Hn + k], Wout[(size_t)o * Hn + k], a);
                }
                a = warp_reduce(a);
                if (lane == 0) out[(size_t)t * OUTn + o] = a + bout[o];
            }
        }
    }
}

extern "C" void kernel_launch(void* const* d_in, const int* in_sizes, int n_in,
                              void* d_out, int out_size) {
    const float* seq  = (const float*)d_in[0];
    const float* Wih1 = (const float*)d_in[1];
    const float* Whh1 = (const float*)d_in[2];
    const float* bih1 = (const float*)d_in[3];
    const float* bhh1 = (const float*)d_in[4];
    const float* Wih2 = (const float*)d_in[5];
    const float* Whh2 = (const float*)d_in[6];
    const float* bih2 = (const float*)d_in[7];
    const float* bhh2 = (const float*)d_in[8];
    const float* Wih3 = (const float*)d_in[9];
    const float* Whh3 = (const float*)d_in[10];
    const float* bih3 = (const float*)d_in[11];
    const float* bhh3 = (const float*)d_in[12];
    const float* Wout = (const float*)d_in[13];
    const float* bout = (const float*)d_in[14];
    float* out = (float*)d_out;

    lstm_persistent_kernel<<<G, TPB>>>(seq,
        Wih1, Whh1, bih1, bhh1,
        Wih2, Whh2, bih2, bhh2,
        Wih3, Whh3, bih3, bhh3,
        Wout, bout, out);
}

// round 3
// speedup vs baseline: 2.6732x; 2.6732x over previous
#include <cuda_runtime.h>
#include <cuda_bf16.h>
#include <cstdint>

#define Tn   4096
#define INn  32
#define Hn   512
#define OUTn 32

#define TPB  512
#define L1C  26          // CTAs for layer 1
#define L23C 52          // CTAs for layers 2 and 3 (each)
#define NCTA (L1C + 2*L23C)   // 130

// -------- persistent device scratch --------
__device__ float g_X1[(size_t)Tn * 4 * Hn];     // x-part of layer 1 incl bias
__device__ float g_h[3][(size_t)Tn * Hn];       // hidden sequences per layer

// sync: slots 0..2 = layer groups, slot 3 = global (X1) barrier
__device__ __align__(128) unsigned long long g_cnt[4 * 16];
__device__ __align__(128) unsigned long long g_gen[4 * 16];

__device__ __forceinline__ void arrive(int slot, int n) {
    __threadfence();
    unsigned long long old = atomicAdd(&g_cnt[slot * 16], 1ULL);
    if (old == (unsigned long long)(n - 1)) {
        g_cnt[slot * 16] = 0ULL;      // safe: no arrival can race (arrivals gated on gen)
        __threadfence();
        atomicAdd(&g_gen[slot * 16], 1ULL);
    }
}
__device__ __forceinline__ void waitgen(int slot, unsigned long long target) {
    volatile unsigned long long* p = &g_gen[slot * 16];
    int it = 0;
    while (*p < target) { if (++it > 32) __nanosleep(64); }
    __threadfence();
}

__device__ __forceinline__ float fast_sig(float x) {
    x = fmaxf(x, -80.0f);
    return __fdividef(1.0f, 1.0f + __expf(-x));
}
__device__ __forceinline__ float fast_tanh(float x) {
    x = fminf(15.0f, fmaxf(-15.0f, x));
    float e = __expf(2.0f * x);
    return __fdividef(e - 1.0f, e + 1.0f);
}

#define RED(v) { v+=__shfl_xor_sync(0xffffffffu,v,16); v+=__shfl_xor_sync(0xffffffffu,v,8); \
                 v+=__shfl_xor_sync(0xffffffffu,v,4);  v+=__shfl_xor_sync(0xffffffffu,v,2); \
                 v+=__shfl_xor_sync(0xffffffffu,v,1); }

__global__ void __launch_bounds__(TPB, 1) lstm_pipe_kernel(
    const float* __restrict__ seq,
    const float* __restrict__ Wih1, const float* __restrict__ Whh1,
    const float* __restrict__ bih1, const float* __restrict__ bhh1,
    const float* __restrict__ Wih2, const float* __restrict__ Whh2,
    const float* __restrict__ bih2, const float* __restrict__ bhh2,
    const float* __restrict__ Wih3, const float* __restrict__ Whh3,
    const float* __restrict__ bih3, const float* __restrict__ bhh3,
    const float* __restrict__ Wout, const float* __restrict__ bout,
    float* __restrict__ out)
{
    __shared__ float sh[Hn];            // own-layer h(t-1)
    __shared__ float sx[Hn];            // prev-layer h(t)
    __shared__ float spA[80];           // partial sums (Whh half / L1 rows)
    __shared__ float spB[40];           // partial sums (Wih half, L2/L3)
    __shared__ float sact[80];          // activated gates
    __shared__ float sc[20];            // cell state
    __shared__ float sbias[40];
    __shared__ float sseq[32 * 33];
    __shared__ unsigned long long sbase[4];

    const int tid = threadIdx.x;
    const int w = tid >> 5;
    const int lane = tid & 31;
    const int cta = blockIdx.x;

    // capture generation bases BEFORE any arrival in this replay
    if (tid < 4) sbase[tid] = *(volatile unsigned long long*)&g_gen[tid * 16];
    __syncthreads();

    // ================= Phase 0: X1 precompute (all CTAs) =================
    {
        int row = cta * 16 + w;
        bool rv = row < 4 * Hn;
        float wx = rv ? Wih1[row * INn + lane] : 0.0f;
        float b1 = rv ? (bih1[row] + bhh1[row]) : 0.0f;
        for (int t0 = 0; t0 < Tn; t0 += 32) {
            __syncthreads();
            if (tid < 256) {
                const float4 v = *(const float4*)(seq + (size_t)t0 * INn + tid * 4);
                int tl = (tid * 4) >> 5, k = (tid * 4) & 31;
                float* p = &sseq[tl * 33 + k];
                p[0] = v.x; p[1] = v.y; p[2] = v.z; p[3] = v.w;
            }
            __syncthreads();
            float acc = 0.0f;
            #pragma unroll
            for (int k = 0; k < INn; k++)
                acc = fmaf(__shfl_sync(0xffffffffu, wx, k), sseq[lane * 33 + k], acc);
            if (rv) g_X1[(size_t)(t0 + lane) * (4 * Hn) + row] = acc + b1;
        }
    }
    // one-time global barrier (slot 3)
    if (tid == 0) { arrive(3, NCTA); waitgen(3, sbase[3] + 1); }
    __syncthreads();

    // ================= group / layer assignment =================
    int layer, cg, gsz;
    if (cta < L1C)              { layer = 0; cg = cta;               gsz = L1C; }
    else if (cta < L1C + L23C)  { layer = 1; cg = cta - L1C;         gsz = L23C; }
    else                        { layer = 2; cg = cta - L1C - L23C;  gsz = L23C; }

    const float* Whh = (layer == 0) ? Whh1 : (layer == 1) ? Whh2 : Whh3;
    const float* Wih = (layer == 1) ? Wih2 : Wih3;
    const float* bih = (layer == 1) ? bih2 : bih3;
    const float* bhh = (layer == 1) ? bhh2 : bhh3;

    // ---- load this warp's 5 half-row weight vectors into registers ----
    float wr[80];
    if (layer == 0) {
        // local rows r = 0..79 : gate = r/20, j = r%20, unit = cg*20 + j (len-512 rows)
        #pragma unroll
        for (int u = 0; u < 5; u++) {
            int r = w * 5 + u;
            int gate = r / 20, j = r % 20;
            int un = cg * 20 + j;
            bool v = un < Hn;
            int R = gate * Hn + (v ? un : 0);
            #pragma unroll
            for (int i = 0; i < 16; i++)
                wr[u * 16 + i] = v ? Whh[(size_t)R * Hn + i * 32 + lane] : 0.0f;
        }
    } else {
        // warps 0..7: Whh half of rows 0..39; warps 8..15: Wih half of rows 0..39
        int half = w >> 3;
        #pragma unroll
        for (int u = 0; u < 5; u++) {
            int r = (w & 7) * 5 + u;
            int gate = r / 10, j = r % 10;
            int un = cg * 10 + j;
            bool v = un < Hn;
            int R = gate * Hn + (v ? un : 0);
            const float* W = half ? Wih : Whh;
            #pragma unroll
            for (int i = 0; i < 16; i++)
                wr[u * 16 + i] = v ? W[(size_t)R * Hn + i * 32 + lane] : 0.0f;
        }
        if (tid < 40) {
            int gate = tid / 10, j = tid % 10;
            int un = cg * 10 + j;
            bool v = un < Hn;
            int R = gate * Hn + (v ? un : 0);
            sbias[tid] = v ? (bih[R] + bhh[R]) : 0.0f;
        }
    }

    // init state
    for (int i = tid; i < Hn; i += TPB) sh[i] = 0.0f;
    if (tid < 20) sc[tid] = 0.0f;
    __syncthreads();

    const unsigned long long mybase = sbase[layer];
    const unsigned long long pbase = (layer > 0) ? sbase[layer - 1] : 0ULL;
    float* hcur = g_h[layer];
    const float* hprev = (layer > 0) ? g_h[layer - 1] : nullptr;

    // ================= pipelined recurrence =================
    for (int t = 0; t < Tn; t++) {
        // prefetch x-part for layer 1 (independent of sync)
        float xv = 0.0f;
        if (layer == 0 && tid < 80) {
            int gate = tid / 20, j = tid % 20;
            int un = cg * 20 + j;
            if (un < Hn) xv = g_X1[(size_t)t * (4 * Hn) + gate * Hn + un];
        }
        // wait: own group done with step t-1; prev layer done with step t
        if (tid == 0) {
            volatile unsigned long long* pown = &g_gen[layer * 16];
            if (layer > 0) {
                volatile unsigned long long* pp = &g_gen[(layer - 1) * 16];
                unsigned long long to = mybase + t, tp = pbase + t + 1;
                int it = 0;
                while (*pown < to || *pp < tp) { if (++it > 32) __nanosleep(64); }
            } else {
                unsigned long long to = mybase + t;
                int it = 0;
                while (*pown < to) { if (++it > 32) __nanosleep(64); }
            }
            __threadfence();
        }
        __syncthreads();

        if (t > 0 && tid < 128)
            *(float4*)&sh[tid * 4] = *(const float4*)(hcur + (size_t)(t - 1) * Hn + tid * 4);
        if (layer > 0 && tid >= 128 && tid < 256)
            *(float4*)&sx[(tid - 128) * 4] = *(const float4*)(hprev + (size_t)t * Hn + (tid - 128) * 4);
        __syncthreads();

        // 5 half-row dots with shared-h reuse
        const float* src = (layer > 0 && w >= 8) ? sx : sh;
        float a0 = 0, a1 = 0, a2 = 0, a3 = 0, a4 = 0;
        #pragma unroll
        for (int i = 0; i < 16; i++) {
            float hv = src[i * 32 + lane];
            a0 = fmaf(wr[i],      hv, a0);
            a1 = fmaf(wr[16 + i], hv, a1);
            a2 = fmaf(wr[32 + i], hv, a2);
            a3 = fmaf(wr[48 + i], hv, a3);
            a4 = fmaf(wr[64 + i], hv, a4);
        }
        RED(a0) RED(a1) RED(a2) RED(a3) RED(a4)
        if (lane < 5) {
            float v = (lane == 0) ? a0 : (lane == 1) ? a1 : (lane == 2) ? a2 : (lane == 3) ? a3 : a4;
            if (layer == 0) spA[w * 5 + lane] = v;
            else            ((w < 8) ? spA : spB)[(w & 7) * 5 + lane] = v;
        }
        __syncthreads();

        // activations (parallel)
        if (layer == 0) {
            if (tid < 80) {
                float gv = spA[tid] + xv;
                int gate = tid / 20;
                sact[tid] = (gate == 2) ? fast_tanh(gv) : fast_sig(gv);
            }
        } else {
            if (tid < 40) {
                float gv = spA[tid] + spB[tid] + sbias[tid];
                int gate = tid / 10;
                sact[tid] = (gate == 2) ? fast_tanh(gv) : fast_sig(gv);
            }
        }
        __syncthreads();

        // c/h update (parallel, one thread per unit)
        int NU = (layer == 0) ? 20 : 10;
        if (tid < NU) {
            int un = cg * NU + tid;
            float iv = sact[tid], fv = sact[NU + tid], gg = sact[2 * NU + tid], ov = sact[3 * NU + tid];
            float c = fmaf(fv, sc[tid], iv * gg);
            sc[tid] = c;
            if (un < Hn) hcur[(size_t)t * Hn + un] = ov * fast_tanh(c);
            __threadfence();
        }
        __syncthreads();
        if (tid == 0) arrive(layer, gsz);
    }

    // ================= final projection (all CTAs, after layer 3 done) =================
    if (tid == 0) waitgen(2, sbase[2] + (unsigned long long)Tn);
    __syncthreads();

    float wo[32];
    const int o0 = w * 2;
    #pragma unroll
    for (int i = 0; i < 16; i++) {
        wo[i]      = Wout[(size_t)o0 * Hn + i * 32 + lane];
        wo[16 + i] = Wout[(size_t)(o0 + 1) * Hn + i * 32 + lane];
    }
    const float b0 = bout[o0], b1o = bout[o0 + 1];
    const float* h3 = g_h[2];
    for (int t = cta; t < Tn; t += NCTA) {
        __syncthreads();
        if (tid < 128)
            *(float4*)&sh[tid * 4] = *(const float4*)(h3 + (size_t)t * Hn + tid * 4);
        __syncthreads();
        float a0 = 0, a1 = 0;
        #pragma unroll
        for (int i = 0; i < 16; i++) {
            float hv = sh[i * 32 + lane];
            a0 = fmaf(wo[i],      hv, a0);
            a1 = fmaf(wo[16 + i], hv, a1);
        }
        RED(a0) RED(a1)
        if (lane == 0) out[(size_t)t * OUTn + o0]     = a0 + b0;
        if (lane == 1) out[(size_t)t * OUTn + o0 + 1] = a1 + b1o;
    }
}

extern "C" void kernel_launch(void* const* d_in, const int* in_sizes, int n_in,
                              void* d_out, int out_size) {
    const float* seq  = (const float*)d_in[0];
    const float* Wih1 = (const float*)d_in[1];
    const float* Whh1 = (const float*)d_in[2];
    const float* bih1 = (const float*)d_in[3];
    const float* bhh1 = (const float*)d_in[4];
    const float* Wih2 = (const float*)d_in[5];
    const float* Whh2 = (const float*)d_in[6];
    const float* bih2 = (const float*)d_in[7];
    const float* bhh2 = (const float*)d_in[8];
    const float* Wih3 = (const float*)d_in[9];
    const float* Whh3 = (const float*)d_in[10];
    const float* bih3 = (const float*)d_in[11];
    const float* bhh3 = (const float*)d_in[12];
    const float* Wout = (const float*)d_in[13];
    const float* bout = (const float*)d_in[14];
    float* out = (float*)d_out;

    lstm_pipe_kernel<<<NCTA, TPB>>>(seq,
        Wih1, Whh1, bih1, bhh1,
        Wih2, Whh2, bih2, bhh2,
        Wih3, Whh3, bih3, bhh3,
        Wout, bout, out);
}

// round 6
// speedup vs baseline: 3.0125x; 1.1269x over previous
#include <cuda_runtime.h>
#include <cuda_bf16.h>
#include <cstdint>

#define Tn   4096
#define INn  32
#define Hn   512
#define OUTn 32

#define TPB  512
#define L1C  26          // CTAs for layer 1 (NU=20 units each)
#define L23C 52          // CTAs for layers 2 and 3 (NU=10 units each)
#define NCTA (L1C + 2*L23C)   // 130

// -------- persistent device scratch --------
__device__ float g_X1[(size_t)Tn * 4 * Hn];
__device__ float g_h[3][(size_t)Tn * Hn];

// per-CTA progress flags, one 128B line each (monotonic across replays)
__device__ __align__(128) unsigned g_flag[3][64][32];
// one-time global barrier (X1 phase)
__device__ __align__(128) unsigned long long g_cnt[16];
__device__ __align__(128) unsigned long long g_gen[16];

__device__ __forceinline__ unsigned ld_acq(const unsigned* p) {
    unsigned v;
    asm volatile("ld.global.acquire.gpu.u32 %0, [%1];" : "=r"(v) : "l"(p) : "memory");
    return v;
}
__device__ __forceinline__ void st_rel(unsigned* p, unsigned v) {
    asm volatile("st.global.release.gpu.u32 [%0], %1;" :: "l"(p), "r"(v) : "memory");
}
__device__ __forceinline__ void ffma2(unsigned long long& d, unsigned long long a, unsigned long long b) {
    asm("fma.rn.f32x2 %0, %1, %2, %0;" : "+l"(d) : "l"(a), "l"(b));
}
__device__ __forceinline__ float f2lo(unsigned long long v) { return __uint_as_float((unsigned)v); }
__device__ __forceinline__ float f2hi(unsigned long long v) { return __uint_as_float((unsigned)(v >> 32)); }

__device__ __forceinline__ float fast_sig(float x) {
    x = fmaxf(x, -80.0f);
    return __fdividef(1.0f, 1.0f + __expf(-x));
}
__device__ __forceinline__ float fast_tanh(float x) {
    x = fminf(15.0f, fmaxf(-15.0f, x));
    float e = __expf(2.0f * x);
    return __fdividef(e - 1.0f, e + 1.0f);
}

#define RED(v) { v+=__shfl_xor_sync(0xffffffffu,v,16); v+=__shfl_xor_sync(0xffffffffu,v,8); \
                 v+=__shfl_xor_sync(0xffffffffu,v,4);  v+=__shfl_xor_sync(0xffffffffu,v,2); \
                 v+=__shfl_xor_sync(0xffffffffu,v,1); }

__global__ void __launch_bounds__(TPB, 1) lstm_flag_kernel(
    const float* __restrict__ seq,
    const float* __restrict__ Wih1, const float* __restrict__ Whh1,
    const float* __restrict__ bih1, const float* __restrict__ bhh1,
    const float* __restrict__ Wih2, const float* __restrict__ Whh2,
    const float* __restrict__ bih2, const float* __restrict__ bhh2,
    const float* __restrict__ Wih3, const float* __restrict__ Whh3,
    const float* __restrict__ bih3, const float* __restrict__ bhh3,
    const float* __restrict__ Wout, const float* __restrict__ bout,
    float* __restrict__ out)
{
    __shared__ float sh[Hn];            // own-layer h(t-1)
    __shared__ float sx[Hn];            // prev-layer h(t)
    __shared__ float spA[80];
    __shared__ float spB[40];
    __shared__ float sact[80];
    __shared__ float sc[20];
    __shared__ float sbias[40];
    __shared__ float sseq[32 * 33];
    __shared__ unsigned sbase[3];
    __shared__ unsigned long long sg3;

    const int tid = threadIdx.x;
    const int w = tid >> 5;
    const int lane = tid & 31;
    const int cta = blockIdx.x;

    // ---- capture flag bases (all layers) BEFORE the global barrier ----
    if (tid < 3) sbase[tid] = *(volatile unsigned*)&g_flag[tid][0][0];
    if (tid == 3) sg3 = *(volatile unsigned long long*)&g_gen[0];
    __syncthreads();

    // ================= Phase 0: X1 precompute =================
    {
        int row = cta * 16 + w;
        bool rv = row < 4 * Hn;
        float wx = rv ? Wih1[row * INn + lane] : 0.0f;
        float b1 = rv ? (bih1[row] + bhh1[row]) : 0.0f;
        for (int t0 = 0; t0 < Tn; t0 += 32) {
            __syncthreads();
            if (tid < 256) {
                const float4 v = *(const float4*)(seq + (size_t)t0 * INn + tid * 4);
                int tl = (tid * 4) >> 5, k = (tid * 4) & 31;
                float* p = &sseq[tl * 33 + k];
                p[0] = v.x; p[1] = v.y; p[2] = v.z; p[3] = v.w;
            }
            __syncthreads();
            float acc = 0.0f;
            #pragma unroll
            for (int k = 0; k < INn; k++)
                acc = fmaf(__shfl_sync(0xffffffffu, wx, k), sseq[lane * 33 + k], acc);
            if (rv) g_X1[(size_t)(t0 + lane) * (4 * Hn) + row] = acc + b1;
        }
    }
    // one-time global barrier
    if (tid == 0) {
        __threadfence();
        unsigned long long old = atomicAdd(&g_cnt[0], 1ULL);
        if (old == (unsigned long long)(NCTA - 1)) {
            g_cnt[0] = 0ULL;
            __threadfence();
            atomicAdd(&g_gen[0], 1ULL);
        }
        volatile unsigned long long* p = &g_gen[0];
        while (*p < sg3 + 1) { }
        __threadfence();
    }
    __syncthreads();

    // ================= group / layer assignment =================
    int layer, cg, gsz, NU, psz, NUp;
    if (cta < L1C)              { layer = 0; cg = cta;               gsz = L1C;  NU = 20; psz = 0;    NUp = 0; }
    else if (cta < L1C + L23C)  { layer = 1; cg = cta - L1C;         gsz = L23C; NU = 10; psz = L1C;  NUp = 20; }
    else                        { layer = 2; cg = cta - L1C - L23C;  gsz = L23C; NU = 10; psz = L23C; NUp = 10; }

    const float* Whh = (layer == 0) ? Whh1 : (layer == 1) ? Whh2 : Whh3;
    const float* Wih = (layer == 1) ? Wih2 : Wih3;
    const float* bih = (layer == 1) ? bih2 : bih3;
    const float* bhh = (layer == 1) ? bhh2 : bhh3;

    // ---- load 5 full 512-long weight rows per warp as f32x2 pairs ----
    unsigned long long wr2[40];
    #pragma unroll
    for (int u = 0; u < 5; u++) {
        int R; bool v;
        if (layer == 0) {
            int r = w * 5 + u;                 // 0..79
            int gate = r / 20, j = r % 20;
            int un = cg * 20 + j;
            v = un < Hn;
            R = gate * Hn + (v ? un : 0);
        } else {
            int rr = (w & 7) * 5 + u;          // 0..39
            int gate = rr / 10, j = rr % 10;
            int un = cg * 10 + j;
            v = un < Hn;
            R = gate * Hn + (v ? un : 0);
        }
        const float* W = (layer == 0) ? Whh : ((w < 8) ? Whh : Wih);
        #pragma unroll
        for (int p = 0; p < 8; p++)
            wr2[u * 8 + p] = v ? *(const unsigned long long*)(W + (size_t)R * Hn + p * 64 + 2 * lane) : 0ULL;
    }
    if (layer > 0 && tid < 40) {
        int gate = tid / 10, j = tid % 10;
        int un = cg * 10 + j;
        bool v = un < Hn;
        int R = gate * Hn + (v ? un : 0);
        sbias[tid] = v ? (bih[R] + bhh[R]) : 0.0f;
    }

    for (int i = tid; i < Hn; i += TPB) { sh[i] = 0.0f; sx[i] = 0.0f; }
    if (tid < 20) sc[tid] = 0.0f;
    __syncthreads();

    const unsigned baseO = sbase[layer];
    const unsigned baseP = (layer > 0) ? sbase[layer - 1] : 0u;
    float* hcur = g_h[layer];
    const float* hprev = (layer > 0) ? g_h[layer - 1] : nullptr;

    // ================= recurrence (pipelined across layer groups) =================
    for (int t = 0; t < Tn; t++) {
        // layer-0 x-part prefetch (in flight during the wait)
        float xv = 0.0f;
        if (layer == 0 && tid < 80) {
            int gate = tid / 20, j = tid % 20;
            int un = cg * 20 + j;
            if (un < Hn) xv = g_X1[(size_t)t * (4 * Hn) + gate * Hn + un];
        }

        // ---- fused wait + chunk load: each poller owns one producer CTA ----
        if (tid < gsz) {
            unsigned tgt = baseO + (unsigned)t;
            const unsigned* fp = &g_flag[layer][tid][0];
            while ((int)(ld_acq(fp) - tgt) < 0) { }
            if (t > 0) {
                const float* src = hcur + (size_t)(t - 1) * Hn + tid * NU;
                int base = tid * NU;
                #pragma unroll 10
                for (int k = 0; k < NU; k += 2) {
                    if (base + k < Hn)
                        *(unsigned long long*)&sh[base + k] = *(const unsigned long long*)(src + k);
                }
            }
        }
        if (layer > 0 && tid >= 64 && tid < 64 + psz) {
            int i = tid - 64;
            unsigned tgt = baseP + (unsigned)(t + 1);
            const unsigned* fp = &g_flag[layer - 1][i][0];
            while ((int)(ld_acq(fp) - tgt) < 0) { }
            const float* src = hprev + (size_t)t * Hn + i * NUp;
            int base = i * NUp;
            #pragma unroll 10
            for (int k = 0; k < NUp; k += 2) {
                if (base + k < Hn)
                    *(unsigned long long*)&sx[base + k] = *(const unsigned long long*)(src + k);
            }
        }
        __syncthreads();

        // ---- 5 x 512 dot products per warp (f32x2 packed FMA) ----
        const float* src = (layer > 0 && w >= 8) ? sx : sh;
        unsigned long long a0 = 0, a1 = 0, a2 = 0, a3 = 0, a4 = 0;
        #pragma unroll
        for (int p = 0; p < 8; p++) {
            unsigned long long hv = *(const unsigned long long*)&src[p * 64 + 2 * lane];
            ffma2(a0, wr2[p],      hv);
            ffma2(a1, wr2[8 + p],  hv);
            ffma2(a2, wr2[16 + p], hv);
            ffma2(a3, wr2[24 + p], hv);
            ffma2(a4, wr2[32 + p], hv);
        }
        float r0 = f2lo(a0) + f2hi(a0);
        float r1 = f2lo(a1) + f2hi(a1);
        float r2 = f2lo(a2) + f2hi(a2);
        float r3 = f2lo(a3) + f2hi(a3);
        float r4 = f2lo(a4) + f2hi(a4);
        RED(r0) RED(r1) RED(r2) RED(r3) RED(r4)
        if (lane < 5) {
            float v = (lane == 0) ? r0 : (lane == 1) ? r1 : (lane == 2) ? r2 : (lane == 3) ? r3 : r4;
            if (layer == 0) spA[w * 5 + lane] = v;
            else            ((w < 8) ? spA : spB)[(w & 7) * 5 + lane] = v;
        }
        __syncthreads();

        // ---- activations ----
        if (layer == 0) {
            if (tid < 80) {
                float gv = spA[tid] + xv;
                int gate = tid / 20;
                sact[tid] = (gate == 2) ? fast_tanh(gv) : fast_sig(gv);
            }
        } else {
            if (tid < 40) {
                float gv = spA[tid] + spB[tid] + sbias[tid];
                int gate = tid / 10;
                sact[tid] = (gate == 2) ? fast_tanh(gv) : fast_sig(gv);
            }
        }
        __syncthreads();

        // ---- c/h update + store ----
        if (tid < NU) {
            int un = cg * NU + tid;
            float iv = sact[tid], fv = sact[NU + tid], gg = sact[2 * NU + tid], ov = sact[3 * NU + tid];
            float c = fmaf(fv, sc[tid], iv * gg);
            sc[tid] = c;
            if (un < Hn) hcur[(size_t)t * Hn + un] = ov * fast_tanh(c);
        }
        __syncthreads();                       // h stores happen-before the release below
        if (tid == 0) st_rel(&g_flag[layer][cg][0], baseO + (unsigned)(t + 1));
    }

    // ================= final projection =================
    if (tid < L23C) {
        unsigned tgt = sbase[2] + (unsigned)Tn;
        const unsigned* fp = &g_flag[2][tid][0];
        while ((int)(ld_acq(fp) - tgt) < 0) { }
    }
    __syncthreads();

    float wo[32];
    const int o0 = w * 2;
    #pragma unroll
    for (int i = 0; i < 16; i++) {
        wo[i]      = Wout[(size_t)o0 * Hn + i * 32 + lane];
        wo[16 + i] = Wout[(size_t)(o0 + 1) * Hn + i * 32 + lane];
    }
    const float b0 = bout[o0], b1o = bout[o0 + 1];
    const float* h3 = g_h[2];
    for (int t = cta; t < Tn; t += NCTA) {
        __syncthreads();
        if (tid < 128)
            *(float4*)&sh[tid * 4] = *(const float4*)(h3 + (size_t)t * Hn + tid * 4);
        __syncthreads();
        float a0 = 0, a1 = 0;
        #pragma unroll
        for (int i = 0; i < 16; i++) {
            float hv = sh[i * 32 + lane];
            a0 = fmaf(wo[i],      hv, a0);
            a1 = fmaf(wo[16 + i], hv, a1);
        }
        RED(a0) RED(a1)
        if (lane == 0) out[(size_t)t * OUTn + o0]     = a0 + b0;
        if (lane == 1) out[(size_t)t * OUTn + o0 + 1] = a1 + b1o;
    }
}

extern "C" void kernel_launch(void* const* d_in, const int* in_sizes, int n_in,
                              void* d_out, int out_size) {
    const float* seq  = (const float*)d_in[0];
    const float* Wih1 = (const float*)d_in[1];
    const float* Whh1 = (const float*)d_in[2];
    const float* bih1 = (const float*)d_in[3];
    const float* bhh1 = (const float*)d_in[4];
    const float* Wih2 = (const float*)d_in[5];
    const float* Whh2 = (const float*)d_in[6];
    const float* bih2 = (const float*)d_in[7];
    const float* bhh2 = (const float*)d_in[8];
    const float* Wih3 = (const float*)d_in[9];
    const float* Whh3 = (const float*)d_in[10];
    const float* bih3 = (const float*)d_in[11];
    const float* bhh3 = (const float*)d_in[12];
    const float* Wout = (const float*)d_in[13];
    const float* bout = (const float*)d_in[14];
    float* out = (float*)d_out;

    lstm_flag_kernel<<<NCTA, TPB>>>(seq,
        Wih1, Whh1, bih1, bhh1,
        Wih2, Whh2, bih2, bhh2,
        Wih3, Whh3, bih3, bhh3,
        Wout, bout, out);
}